// round 16
// baseline (speedup 1.0000x reference)
#include <cuda_runtime.h>
#include <cuda_fp16.h>
#include <math.h>
#include <stdint.h>

// ---------------- problem constants ----------------
#define BB 4
#define SS 1024
#define DD 1024
#define HH 16
#define DHH 64
#define FFN 4096
#define ROWS (BB*SS)   // 4096

// ---------------- device scratch ----------------
__device__ float  g_o1 [ROWS*DD];
__device__ __half g_x  [ROWS*DD];               // LN out / attn out
__device__ __half g_mid[(size_t)ROWS*FFN];
__device__ __half g_qkv[3 * ROWS * DD];         // q|k|v in (B,H,S,DH)
__device__ float  g_bqkv[3 * DD];               // fused qkv bias
// transposed fp16 weights, layout [N,K] K-major
__device__ __half g_wqkvt[(size_t)3 * DD * DD]; // wq|wk|wv rows
__device__ __half g_wot[DD*DD];
__device__ __half g_w1t[(size_t)DD*FFN];
__device__ __half g_w2t[(size_t)DD*FFN];

// ---------------- small helpers ----------------
__device__ __forceinline__ uint32_t smem_u32(const void* p) {
    uint32_t a;
    asm("{ .reg .u64 t; cvta.to.shared.u64 t, %1; cvt.u32.u64 %0, t; }" : "=r"(a) : "l"(p));
    return a;
}
__device__ __forceinline__ void cp_async16(uint32_t s, const void* g) {
    asm volatile("cp.async.cg.shared.global [%0], [%1], 16;" :: "r"(s), "l"(g));
}
__device__ __forceinline__ void ldsm_x4(uint32_t* r, uint32_t addr) {
    asm volatile("ldmatrix.sync.aligned.m8n8.x4.shared.b16 {%0,%1,%2,%3}, [%4];"
        : "=r"(r[0]), "=r"(r[1]), "=r"(r[2]), "=r"(r[3]) : "r"(addr));
}
__device__ __forceinline__ void ldsm_x4_t(uint32_t* r, uint32_t addr) {
    asm volatile("ldmatrix.sync.aligned.m8n8.x4.trans.shared.b16 {%0,%1,%2,%3}, [%4];"
        : "=r"(r[0]), "=r"(r[1]), "=r"(r[2]), "=r"(r[3]) : "r"(addr));
}
__device__ __forceinline__ void mma16816(float* d, const uint32_t* a, const uint32_t* b) {
    asm volatile("mma.sync.aligned.m16n8k16.row.col.f32.f16.f16.f32 "
        "{%0,%1,%2,%3}, {%4,%5,%6,%7}, {%8,%9}, {%0,%1,%2,%3};"
        : "+f"(d[0]), "+f"(d[1]), "+f"(d[2]), "+f"(d[3])
        : "r"(a[0]), "r"(a[1]), "r"(a[2]), "r"(a[3]), "r"(b[0]), "r"(b[1]));
}
__device__ __forceinline__ uint32_t pack_h2(__half a, __half b) {
    __half2 t = __halves2half2(a, b);
    return *(uint32_t*)&t;
}

// ---------------- mega kernel: weight conversions + bias pack + LN1 -------
__global__ void wconv_all(const float* __restrict__ wq, const float* __restrict__ wk,
                          const float* __restrict__ wv, const float* __restrict__ wo,
                          const float* __restrict__ w1, const float* __restrict__ w2,
                          const float* __restrict__ bq, const float* __restrict__ bk,
                          const float* __restrict__ bv,
                          const float* __restrict__ x, const float* __restrict__ g1,
                          const float* __restrict__ b1, __half* __restrict__ xa)
{
    int bid = blockIdx.x;
    int tx = threadIdx.x, ty = threadIdx.y;   // 32 x 8
    int t = ty * 32 + tx;
    __shared__ float tl[32][33];
    __shared__ float red0[8], red1[8];

    if (bid >= 12289) {
        int row = bid - 12289;
        const float4* xr = (const float4*)(x + (size_t)row * DD);
        float4 v = xr[t];
        float s  = v.x + v.y + v.z + v.w;
        float s2 = v.x*v.x + v.y*v.y + v.z*v.z + v.w*v.w;
        #pragma unroll
        for (int o = 16; o; o >>= 1) {
            s  += __shfl_xor_sync(0xffffffffu, s,  o);
            s2 += __shfl_xor_sync(0xffffffffu, s2, o);
        }
        if ((t & 31) == 0) { red0[t >> 5] = s; red1[t >> 5] = s2; }
        __syncthreads();
        float S = 0.f, S2 = 0.f;
        #pragma unroll
        for (int i = 0; i < 8; i++) { S += red0[i]; S2 += red1[i]; }
        float mean = S * (1.f / DD);
        float var  = S2 * (1.f / DD) - mean * mean;
        float rstd = rsqrtf(var + 1e-5f);
        float4 gv = ((const float4*)g1)[t];
        float4 bv4 = ((const float4*)b1)[t];
        float o0 = (v.x - mean) * rstd * gv.x + bv4.x;
        float o1 = (v.y - mean) * rstd * gv.y + bv4.y;
        float o2 = (v.z - mean) * rstd * gv.z + bv4.z;
        float o3 = (v.w - mean) * rstd * gv.w + bv4.w;
        size_t base = (size_t)row * DD + t * 4;
        *(__half2*)(xa + base)     = __halves2half2(__float2half_rn(o0), __float2half_rn(o1));
        *(__half2*)(xa + base + 2) = __halves2half2(__float2half_rn(o2), __float2half_rn(o3));
        return;
    }
    if (bid == 12288) {
        for (int i = t; i < DD; i += 256) {
            g_bqkv[i]        = bq[i];
            g_bqkv[DD + i]   = bk[i];
            g_bqkv[2*DD + i] = bv[i];
        }
        return;
    }
    const float* W; __half* T; int K, N, tile, rowoff = 0;
    if (bid < 3072)      { int wsel = bid >> 10; W = wsel == 0 ? wq : (wsel == 1 ? wk : wv);
                           T = g_wqkvt; K = DD; N = DD; tile = bid & 1023; rowoff = wsel * DD; }
    else if (bid < 4096) { W = wo; T = g_wot; K = DD;  N = DD;  tile = bid - 3072; }
    else if (bid < 8192) { W = w1; T = g_w1t; K = DD;  N = FFN; tile = bid - 4096; }
    else                 { W = w2; T = g_w2t; K = FFN; N = DD;  tile = bid - 8192; }
    int ntiles_n = N >> 5;
    int k0 = (tile / ntiles_n) << 5;
    int n0 = (tile % ntiles_n) << 5;

    #pragma unroll
    for (int i = 0; i < 4; i++)
        tl[ty + i*8][tx] = W[(size_t)(k0 + ty + i*8) * N + n0 + tx];
    __syncthreads();
    #pragma unroll
    for (int i = 0; i < 4; i++) {
        int n = n0 + ty + i*8;
        int k = k0 + tx;
        T[(size_t)(rowoff + n) * K + k] = __float2half_rn(tl[tx][ty + i*8]);
    }
}

// ---------------- LayerNorm -> fp16 (LN2) ----------------
__global__ void layernorm_f16(const float* __restrict__ x, const float* __restrict__ g,
                              const float* __restrict__ b, __half* __restrict__ oh)
{
    __shared__ float red0[8], red1[8];
    int row = blockIdx.x, tid = threadIdx.x;
    const float4* xr = (const float4*)(x + (size_t)row * DD);
    float4 v = xr[tid];
    float s  = v.x + v.y + v.z + v.w;
    float s2 = v.x*v.x + v.y*v.y + v.z*v.z + v.w*v.w;
    #pragma unroll
    for (int o = 16; o; o >>= 1) {
        s  += __shfl_xor_sync(0xffffffffu, s,  o);
        s2 += __shfl_xor_sync(0xffffffffu, s2, o);
    }
    if ((tid & 31) == 0) { red0[tid >> 5] = s; red1[tid >> 5] = s2; }
    __syncthreads();
    float S = 0.f, S2 = 0.f;
    #pragma unroll
    for (int i = 0; i < 8; i++) { S += red0[i]; S2 += red1[i]; }
    float mean = S * (1.f / DD);
    float var  = S2 * (1.f / DD) - mean * mean;
    float rstd = rsqrtf(var + 1e-5f);
    float4 gv = ((const float4*)g)[tid];
    float4 bv = ((const float4*)b)[tid];
    float o0 = (v.x - mean) * rstd * gv.x + bv.x;
    float o1 = (v.y - mean) * rstd * gv.y + bv.y;
    float o2 = (v.z - mean) * rstd * gv.z + bv.z;
    float o3 = (v.w - mean) * rstd * gv.w + bv.w;
    size_t base = (size_t)row * DD + tid * 4;
    *(__half2*)(oh + base)     = __halves2half2(__float2half_rn(o0), __float2half_rn(o1));
    *(__half2*)(oh + base + 2) = __halves2half2(__float2half_rn(o2), __float2half_rn(o3));
}

// ---------------- tensor-core GEMM, fp16 1-pass, 4-stage single-sync ------
// block 128x128, 8 warps, warp tile 32x64, BK=32, 2 CTAs/SM.
// R15/16: all 28 ldsm issued up-front into distinct register arrays so the
// B-ks1 loads are in flight during the ks0 MMA burst. Loads for stage kc+3
// stay AFTER compute (R11-verified placement).
#define LDB 80
#define ARR 10240
#define STG_SZ 20480
#define GSTAGES 4
template<int EPI>
__global__ void __launch_bounds__(256, 2)
gemm_mma(const __half* __restrict__ A, const __half* __restrict__ W,
         const float* __restrict__ bias, const float* __restrict__ res,
         float* __restrict__ C, __half* __restrict__ Ch,
         int M, int N, int K)
{
    extern __shared__ char smem[];
    const uint32_t sb = smem_u32(smem);
    const int tid = threadIdx.x;
    const int wid = tid >> 5, lane = tid & 31;
    const int wm = wid & 3, wn = wid >> 2;
    const int m0 = blockIdx.y * 128, n0 = blockIdx.x * 128;

    float acc[2][8][4] = {};
    const int NK = K >> 5;

    auto load_stage = [&](int kc, int buf) {
        int k0 = kc << 5;
        uint32_t stb = sb + buf * STG_SZ;
        #pragma unroll
        for (int i = 0; i < 4; i++) {
            int c = tid + i * 256;
            int arr = c >> 9;
            int cc = c & 511;
            int row = cc >> 2, col = cc & 3;
            const __half* gsrc = (arr ? W + (size_t)(n0 + row) * K
                                      : A + (size_t)(m0 + row) * K) + k0 + col * 8;
            cp_async16(stb + arr * ARR + row * LDB + col * 16, gsrc);
        }
    };

    // prologue: stages 0,1,2 (groups 0,1,2)
    load_stage(0, 0);
    asm volatile("cp.async.commit_group;" ::: "memory");
    load_stage(1, 1);
    asm volatile("cp.async.commit_group;" ::: "memory");
    load_stage(2, 2);
    asm volatile("cp.async.commit_group;" ::: "memory");

    for (int kc = 0; kc < NK; kc++) {
        asm volatile("cp.async.wait_group 2;" ::: "memory");
        __syncthreads();

        uint32_t stb = sb + (kc & 3) * STG_SZ;

        // ---- issue ALL fragment loads up-front (28 ldsm) ----
        uint32_t Af[2][2][4];        // [ks][mt]
        uint32_t Bf0[8][2], Bf1[8][2];
        int ar = lane & 15;
        int acq = (lane >> 4) * 8;
        #pragma unroll
        for (int ks = 0; ks < 2; ks++)
            #pragma unroll
            for (int mt = 0; mt < 2; mt++)
                ldsm_x4(Af[ks][mt],
                        stb + (wm * 32 + mt * 16 + ar) * LDB + (ks * 16 + acq) * 2);
        int gq = lane >> 3, l8 = lane & 7;
        int br = (gq >> 1) * 8 + l8;
        int bc0 = (gq & 1) * 8, bc1 = 16 + (gq & 1) * 8;
        #pragma unroll
        for (int p = 0; p < 4; p++) {
            uint32_t a0 = stb + ARR + (wn * 64 + p * 16 + br) * LDB + bc0 * 2;
            uint32_t t4[4];
            ldsm_x4(t4, a0);
            Bf0[2*p][0] = t4[0]; Bf0[2*p][1] = t4[1];
            Bf0[2*p+1][0] = t4[2]; Bf0[2*p+1][1] = t4[3];
        }
        #pragma unroll
        for (int p = 0; p < 4; p++) {
            uint32_t a1 = stb + ARR + (wn * 64 + p * 16 + br) * LDB + bc1 * 2;
            uint32_t t4[4];
            ldsm_x4(t4, a1);
            Bf1[2*p][0] = t4[0]; Bf1[2*p][1] = t4[1];
            Bf1[2*p+1][0] = t4[2]; Bf1[2*p+1][1] = t4[3];
        }

        // ---- MMA bursts: ks0 (B-ks1 ldsm still in flight), then ks1 ----
        #pragma unroll
        for (int mt = 0; mt < 2; mt++)
            #pragma unroll
            for (int nt = 0; nt < 8; nt++)
                mma16816(acc[mt][nt], Af[0][mt], Bf0[nt]);
        #pragma unroll
        for (int mt = 0; mt < 2; mt++)
            #pragma unroll
            for (int nt = 0; nt < 8; nt++)
                mma16816(acc[mt][nt], Af[1][mt], Bf1[nt]);

        // issue next stage (group kc+3); empty commit keeps group numbering
        if (kc + 3 < NK) load_stage(kc + 3, (kc + 3) & 3);
        asm volatile("cp.async.commit_group;" ::: "memory");
    }

    // ---- epilogue ----
    int rb = m0 + wm * 32 + (lane >> 2);
    int cb = n0 + wn * 64 + (lane & 3) * 2;
    #pragma unroll
    for (int mt = 0; mt < 2; mt++) {
        #pragma unroll
        for (int half = 0; half < 2; half++) {
            int r = rb + mt * 16 + half * 8;
            #pragma unroll
            for (int nt = 0; nt < 8; nt++) {
                int n = cb + nt * 8;
                float2 bv = *(const float2*)(bias + n);
                float v0 = acc[mt][nt][half * 2 + 0] + bv.x;
                float v1 = acc[mt][nt][half * 2 + 1] + bv.y;
                if (EPI == 2) {
                    float2 rv = *(const float2*)(res + (size_t)r * N + n);
                    v0 += rv.x; v1 += rv.y;
                    *(float2*)(C + (size_t)r * N + n) = make_float2(v0, v1);
                } else if (EPI == 3) {
                    v0 = 0.5f * v0 * (1.0f + erff(v0 * 0.70710678118654752f));
                    v1 = 0.5f * v1 * (1.0f + erff(v1 * 0.70710678118654752f));
                    *(__half2*)(Ch + (size_t)r * N + n) =
                        __halves2half2(__float2half_rn(v0), __float2half_rn(v1));
                } else if (EPI == 4) {
                    int which = n >> 10, n2 = n & 1023;
                    float scl = (which == 0) ? (1.0f / 32.0f) : 1.0f;
                    v0 *= scl; v1 *= scl;
                    int b_ = r >> 10, s = r & 1023, hh = n2 >> 6, dh = n2 & 63;
                    size_t off = (size_t)which * (ROWS * DD)
                               + ((size_t)(b_ * HH + hh) * SS + s) * DHH + dh;
                    *(__half2*)(Ch + off) =
                        __halves2half2(__float2half_rn(v0), __float2half_rn(v1));
                }
            }
        }
    }
}

// ---------------- Flash attention, fp16, 4-stage single-sync KV -----------
#define LDK 144
#define FQ_SZ 18432
#define FST0  18432
#define FARR  9216
#define FST_SZ 18432
#define FSTAGES 4
#define FLASH_SMEM (FST0 + FSTAGES*FST_SZ)   // 92160
__global__ void __launch_bounds__(256, 2)
flash_mma(const __half* __restrict__ Q_, const __half* __restrict__ K_,
          const __half* __restrict__ V_, __half* __restrict__ O_)
{
    extern __shared__ char smc[];
    const uint32_t sb = smem_u32(smc);
    int tid = threadIdx.x, lane = tid & 31, w = tid >> 5;
    int bh = blockIdx.y, q0 = blockIdx.x * 128;
    size_t qbase = ((size_t)bh * SS + q0) * DHH;
    size_t kvbase = (size_t)bh * SS * DHH;
    const int NT = SS / 64;

    // group 0: Q
    #pragma unroll
    for (int i = 0; i < 4; i++) {
        int c = tid + i * 256;
        int row = c >> 3, col = c & 7;
        cp_async16(sb + row * LDK + col * 16, Q_ + qbase + row * 64 + col * 8);
    }
    asm volatile("cp.async.commit_group;" ::: "memory");
    auto load_stage = [&](int t, int buf) {
        size_t base = kvbase + (size_t)t * 64 * DHH;
        #pragma unroll
        for (int i = 0; i < 4; i++) {
            int c = tid + i * 256;
            int arr = c >> 9, cc = c & 511;
            int row = cc >> 3, col = cc & 7;
            const __half* src = (arr ? V_ : K_) + base + row * 64 + col * 8;
            cp_async16(sb + FST0 + buf * FST_SZ + arr * FARR + row * LDK + col * 16, src);
        }
    };
    // groups 1..3: stages 0..2
    load_stage(0, 0);
    asm volatile("cp.async.commit_group;" ::: "memory");
    load_stage(1, 1);
    asm volatile("cp.async.commit_group;" ::: "memory");
    load_stage(2, 2);
    asm volatile("cp.async.commit_group;" ::: "memory");

    uint32_t qf[4][4];
    float m2[2] = {-1e30f, -1e30f}, l2[2] = {0.f, 0.f};
    float acc_o[8][4] = {};

    for (int t = 0; t < NT; t++) {
        asm volatile("cp.async.wait_group 2;" ::: "memory");
        __syncthreads();
        if (t == 0) {
            #pragma unroll
            for (int ks = 0; ks < 4; ks++)
                ldsm_x4(qf[ks], sb + (w * 16 + (lane & 15)) * LDK + ks * 32 + (lane >> 4) * 16);
        }
        uint32_t stb = sb + FST0 + (t & 3) * FST_SZ;

        float s[8][4] = {};
        int gq = lane >> 3, l8 = lane & 7;
        int br = (gq >> 1) * 8 + l8;
        #pragma unroll
        for (int ks = 0; ks < 4; ks++) {
            uint32_t Bf[8][2];
            int bcB = ks * 32 + (gq & 1) * 16;
            #pragma unroll
            for (int p = 0; p < 4; p++) {
                uint32_t a = stb + (p * 16 + br) * LDK + bcB;
                uint32_t t4[4];
                ldsm_x4(t4, a);
                Bf[2*p][0] = t4[0]; Bf[2*p][1] = t4[1];
                Bf[2*p+1][0] = t4[2]; Bf[2*p+1][1] = t4[3];
            }
            #pragma unroll
            for (int nt = 0; nt < 8; nt++)
                mma16816(s[nt], qf[ks], Bf[nt]);
        }

        float rm0 = -1e30f, rm1 = -1e30f;
        #pragma unroll
        for (int nt = 0; nt < 8; nt++) {
            rm0 = fmaxf(rm0, fmaxf(s[nt][0], s[nt][1]));
            rm1 = fmaxf(rm1, fmaxf(s[nt][2], s[nt][3]));
        }
        rm0 = fmaxf(rm0, __shfl_xor_sync(0xffffffffu, rm0, 1));
        rm0 = fmaxf(rm0, __shfl_xor_sync(0xffffffffu, rm0, 2));
        rm1 = fmaxf(rm1, __shfl_xor_sync(0xffffffffu, rm1, 1));
        rm1 = fmaxf(rm1, __shfl_xor_sync(0xffffffffu, rm1, 2));
        float mn0 = fmaxf(m2[0], rm0), mn1 = fmaxf(m2[1], rm1);
        float al0 = __expf(m2[0] - mn0), al1 = __expf(m2[1] - mn1);
        float rs0 = 0.f, rs1 = 0.f;
        #pragma unroll
        for (int nt = 0; nt < 8; nt++) {
            s[nt][0] = __expf(s[nt][0] - mn0);
            s[nt][1] = __expf(s[nt][1] - mn0);
            s[nt][2] = __expf(s[nt][2] - mn1);
            s[nt][3] = __expf(s[nt][3] - mn1);
            rs0 += s[nt][0] + s[nt][1];
            rs1 += s[nt][2] + s[nt][3];
        }
        rs0 += __shfl_xor_sync(0xffffffffu, rs0, 1);
        rs0 += __shfl_xor_sync(0xffffffffu, rs0, 2);
        rs1 += __shfl_xor_sync(0xffffffffu, rs1, 1);
        rs1 += __shfl_xor_sync(0xffffffffu, rs1, 2);
        l2[0] = l2[0] * al0 + rs0;
        l2[1] = l2[1] * al1 + rs1;
        m2[0] = mn0; m2[1] = mn1;
        #pragma unroll
        for (int nt = 0; nt < 8; nt++) {
            acc_o[nt][0] *= al0; acc_o[nt][1] *= al0;
            acc_o[nt][2] *= al1; acc_o[nt][3] *= al1;
        }

        int vr = ((lane >> 3) & 1) * 8 + (lane & 7);
        int vcb = ((lane >> 4) * 8) * 2;
        #pragma unroll
        for (int ks = 0; ks < 4; ks++) {
            uint32_t pf[4];
            #pragma unroll
            for (int q2 = 0; q2 < 2; q2++) {
                pf[2*q2]     = pack_h2(__float2half_rn(s[2*ks + q2][0]), __float2half_rn(s[2*ks + q2][1]));
                pf[2*q2 + 1] = pack_h2(__float2half_rn(s[2*ks + q2][2]), __float2half_rn(s[2*ks + q2][3]));
            }
            uint32_t Vf[8][2];
            #pragma unroll
            for (int np = 0; np < 4; np++) {
                uint32_t a = stb + FARR + (ks * 16 + vr) * LDK + np * 32 + vcb;
                uint32_t t4[4];
                ldsm_x4_t(t4, a);
                Vf[2*np][0] = t4[0]; Vf[2*np][1] = t4[1];
                Vf[2*np+1][0] = t4[2]; Vf[2*np+1][1] = t4[3];
            }
            #pragma unroll
            for (int nt = 0; nt < 8; nt++)
                mma16816(acc_o[nt], pf, Vf[nt]);
        }

        // issue next stage (group 4+t = stage t+3); empty commit otherwise
        if (t + 3 < NT) load_stage(t + 3, (t + 3) & 3);
        asm volatile("cp.async.commit_group;" ::: "memory");
    }

    float inv0 = 1.0f / l2[0], inv1 = 1.0f / l2[1];
    int g = lane >> 2;
    int bb = bh >> 4, hh = bh & 15;
    int r_lo = q0 + w * 16 + g, r_hi = r_lo + 8;
    int cbase = hh * 64 + (lane & 3) * 2;
    #pragma unroll
    for (int nt = 0; nt < 8; nt++) {
        int cc = cbase + nt * 8;
        size_t off_lo = ((size_t)bb * SS + r_lo) * DD + cc;
        size_t off_hi = ((size_t)bb * SS + r_hi) * DD + cc;
        *(__half2*)(O_ + off_lo) = __halves2half2(
            __float2half_rn(acc_o[nt][0] * inv0), __float2half_rn(acc_o[nt][1] * inv0));
        *(__half2*)(O_ + off_hi) = __halves2half2(
            __float2half_rn(acc_o[nt][2] * inv1), __float2half_rn(acc_o[nt][3] * inv1));
    }
}

// ---------------- launch ----------------
extern "C" void kernel_launch(void* const* d_in, const int* in_sizes, int n_in,
                              void* d_out, int out_size)
{
    const float* x    = (const float*)d_in[0];
    const float* wq   = (const float*)d_in[1];
    const float* bq   = (const float*)d_in[2];
    const float* wk   = (const float*)d_in[3];
    const float* bk   = (const float*)d_in[4];
    const float* wv   = (const float*)d_in[5];
    const float* bv   = (const float*)d_in[6];
    const float* wo   = (const float*)d_in[7];
    const float* bo   = (const float*)d_in[8];
    const float* g1   = (const float*)d_in[9];
    const float* b1   = (const float*)d_in[10];
    const float* g2   = (const float*)d_in[11];
    const float* b2   = (const float*)d_in[12];
    const float* wfc1 = (const float*)d_in[13];
    const float* bfc1 = (const float*)d_in[14];
    const float* wfc2 = (const float*)d_in[15];
    const float* bfc2 = (const float*)d_in[16];
    float* out = (float*)d_out;

    float *o1, *bqkv;
    cudaGetSymbolAddress((void**)&o1,   g_o1);
    cudaGetSymbolAddress((void**)&bqkv, g_bqkv);
    __half *xa, *mid, *qkv;
    cudaGetSymbolAddress((void**)&xa,  g_x);
    cudaGetSymbolAddress((void**)&mid, g_mid);
    cudaGetSymbolAddress((void**)&qkv, g_qkv);
    __half *wqkvt, *wot, *w1t, *w2t;
    cudaGetSymbolAddress((void**)&wqkvt, g_wqkvt);
    cudaGetSymbolAddress((void**)&wot,   g_wot);
    cudaGetSymbolAddress((void**)&w1t,   g_w1t);
    cudaGetSymbolAddress((void**)&w2t,   g_w2t);

    const int GEMM_SMEM = GSTAGES * STG_SZ;  // 81920
    cudaFuncSetAttribute(gemm_mma<2>, cudaFuncAttributeMaxDynamicSharedMemorySize, GEMM_SMEM);
    cudaFuncSetAttribute(gemm_mma<3>, cudaFuncAttributeMaxDynamicSharedMemorySize, GEMM_SMEM);
    cudaFuncSetAttribute(gemm_mma<4>, cudaFuncAttributeMaxDynamicSharedMemorySize, GEMM_SMEM);
    cudaFuncSetAttribute(flash_mma, cudaFuncAttributeMaxDynamicSharedMemorySize, FLASH_SMEM);

    // 0. weights + bias pack + LN1, one launch
    wconv_all<<<16385, dim3(32, 8)>>>(wq, wk, wv, wo, wfc1, wfc2, bq, bk, bv,
                                      x, g1, b1, xa);

    // 1. fused QKV projection -> (3,B,H,S,DH) fp16
    gemm_mma<4><<<dim3(3 * DD / 128, ROWS / 128), 256, GEMM_SMEM>>>(
        xa, wqkvt, bqkv, nullptr, nullptr, qkv, ROWS, 3 * DD, DD);

    // 2. attention -> fp16 (B,S,D) into xa
    flash_mma<<<dim3(SS / 128, BB * HH), 256, FLASH_SMEM>>>(
        qkv, qkv + ROWS * DD, qkv + 2 * ROWS * DD, xa);

    // 3. output projection + residual(x) -> o1 fp32
    gemm_mma<2><<<dim3(DD / 128, ROWS / 128), 256, GEMM_SMEM>>>(
        xa, wot, bo, x, o1, nullptr, ROWS, DD, DD);

    // 4. LN2 -> fp16
    layernorm_f16<<<ROWS, 256>>>(o1, g2, b2, xa);

    // 5. FC1 + GELU -> fp16 mid
    gemm_mma<3><<<dim3(FFN / 128, ROWS / 128), 256, GEMM_SMEM>>>(
        xa, w1t, bfc1, nullptr, nullptr, mid, ROWS, FFN, DD);

    // 6. FC2 + residual(o1) -> out
    gemm_mma<2><<<dim3(DD / 128, ROWS / 128), 256, GEMM_SMEM>>>(
        mid, w2t, bfc2, o1, out, nullptr, ROWS, DD, FFN);
}

// round 17
// speedup vs baseline: 1.0594x; 1.0594x over previous
#include <cuda_runtime.h>
#include <cuda_fp16.h>
#include <math.h>
#include <stdint.h>

// ---------------- problem constants ----------------
#define BB 4
#define SS 1024
#define DD 1024
#define HH 16
#define DHH 64
#define FFN 4096
#define ROWS (BB*SS)   // 4096

// ---------------- device scratch ----------------
__device__ float  g_o1 [ROWS*DD];
__device__ __half g_x  [ROWS*DD];               // LN out / attn out
__device__ __half g_mid[(size_t)ROWS*FFN];
__device__ __half g_qkv[3 * ROWS * DD];         // q|k|v in (B,H,S,DH)
__device__ float  g_bqkv[3 * DD];               // fused qkv bias
// transposed fp16 weights, layout [N,K] K-major
__device__ __half g_wqkvt[(size_t)3 * DD * DD]; // wq|wk|wv rows
__device__ __half g_wot[DD*DD];
__device__ __half g_w1t[(size_t)DD*FFN];
__device__ __half g_w2t[(size_t)DD*FFN];

// ---------------- small helpers ----------------
__device__ __forceinline__ uint32_t smem_u32(const void* p) {
    uint32_t a;
    asm("{ .reg .u64 t; cvta.to.shared.u64 t, %1; cvt.u32.u64 %0, t; }" : "=r"(a) : "l"(p));
    return a;
}
__device__ __forceinline__ void cp_async16(uint32_t s, const void* g) {
    asm volatile("cp.async.cg.shared.global [%0], [%1], 16;" :: "r"(s), "l"(g));
}
__device__ __forceinline__ void ldsm_x4(uint32_t* r, uint32_t addr) {
    asm volatile("ldmatrix.sync.aligned.m8n8.x4.shared.b16 {%0,%1,%2,%3}, [%4];"
        : "=r"(r[0]), "=r"(r[1]), "=r"(r[2]), "=r"(r[3]) : "r"(addr));
}
__device__ __forceinline__ void ldsm_x4_t(uint32_t* r, uint32_t addr) {
    asm volatile("ldmatrix.sync.aligned.m8n8.x4.trans.shared.b16 {%0,%1,%2,%3}, [%4];"
        : "=r"(r[0]), "=r"(r[1]), "=r"(r[2]), "=r"(r[3]) : "r"(addr));
}
__device__ __forceinline__ void mma16816(float* d, const uint32_t* a, const uint32_t* b) {
    asm volatile("mma.sync.aligned.m16n8k16.row.col.f32.f16.f16.f32 "
        "{%0,%1,%2,%3}, {%4,%5,%6,%7}, {%8,%9}, {%0,%1,%2,%3};"
        : "+f"(d[0]), "+f"(d[1]), "+f"(d[2]), "+f"(d[3])
        : "r"(a[0]), "r"(a[1]), "r"(a[2]), "r"(a[3]), "r"(b[0]), "r"(b[1]));
}
__device__ __forceinline__ uint32_t pack_h2(__half a, __half b) {
    __half2 t = __halves2half2(a, b);
    return *(uint32_t*)&t;
}

// ---------------- mega kernel: weight conversions + bias pack + LN1 -------
// Transpose writeback vectorized: each thread stores 4 contiguous k as 8B.
__global__ void wconv_all(const float* __restrict__ wq, const float* __restrict__ wk,
                          const float* __restrict__ wv, const float* __restrict__ wo,
                          const float* __restrict__ w1, const float* __restrict__ w2,
                          const float* __restrict__ bq, const float* __restrict__ bk,
                          const float* __restrict__ bv,
                          const float* __restrict__ x, const float* __restrict__ g1,
                          const float* __restrict__ b1, __half* __restrict__ xa)
{
    int bid = blockIdx.x;
    int tx = threadIdx.x, ty = threadIdx.y;   // 32 x 8
    int t = ty * 32 + tx;
    __shared__ float tl[32][33];
    __shared__ float red0[8], red1[8];

    if (bid >= 12289) {
        int row = bid - 12289;
        const float4* xr = (const float4*)(x + (size_t)row * DD);
        float4 v = xr[t];
        float s  = v.x + v.y + v.z + v.w;
        float s2 = v.x*v.x + v.y*v.y + v.z*v.z + v.w*v.w;
        #pragma unroll
        for (int o = 16; o; o >>= 1) {
            s  += __shfl_xor_sync(0xffffffffu, s,  o);
            s2 += __shfl_xor_sync(0xffffffffu, s2, o);
        }
        if ((t & 31) == 0) { red0[t >> 5] = s; red1[t >> 5] = s2; }
        __syncthreads();
        float S = 0.f, S2 = 0.f;
        #pragma unroll
        for (int i = 0; i < 8; i++) { S += red0[i]; S2 += red1[i]; }
        float mean = S * (1.f / DD);
        float var  = S2 * (1.f / DD) - mean * mean;
        float rstd = rsqrtf(var + 1e-5f);
        float4 gv = ((const float4*)g1)[t];
        float4 bv4 = ((const float4*)b1)[t];
        float o0 = (v.x - mean) * rstd * gv.x + bv4.x;
        float o1 = (v.y - mean) * rstd * gv.y + bv4.y;
        float o2 = (v.z - mean) * rstd * gv.z + bv4.z;
        float o3 = (v.w - mean) * rstd * gv.w + bv4.w;
        size_t base = (size_t)row * DD + t * 4;
        *(__half2*)(xa + base)     = __halves2half2(__float2half_rn(o0), __float2half_rn(o1));
        *(__half2*)(xa + base + 2) = __halves2half2(__float2half_rn(o2), __float2half_rn(o3));
        return;
    }
    if (bid == 12288) {
        for (int i = t; i < DD; i += 256) {
            g_bqkv[i]        = bq[i];
            g_bqkv[DD + i]   = bk[i];
            g_bqkv[2*DD + i] = bv[i];
        }
        return;
    }
    const float* W; __half* T; int K, N, tile, rowoff = 0;
    if (bid < 3072)      { int wsel = bid >> 10; W = wsel == 0 ? wq : (wsel == 1 ? wk : wv);
                           T = g_wqkvt; K = DD; N = DD; tile = bid & 1023; rowoff = wsel * DD; }
    else if (bid < 4096) { W = wo; T = g_wot; K = DD;  N = DD;  tile = bid - 3072; }
    else if (bid < 8192) { W = w1; T = g_w1t; K = DD;  N = FFN; tile = bid - 4096; }
    else                 { W = w2; T = g_w2t; K = FFN; N = DD;  tile = bid - 8192; }
    int ntiles_n = N >> 5;
    int k0 = (tile / ntiles_n) << 5;
    int n0 = (tile % ntiles_n) << 5;

    #pragma unroll
    for (int i = 0; i < 4; i++)
        tl[ty + i*8][tx] = W[(size_t)(k0 + ty + i*8) * N + n0 + tx];
    __syncthreads();
    // vectorized writeback: thread t handles n = n0 + (t>>3), k = k0 + (t&7)*4 .. +3
    {
        int n = n0 + (t >> 3);
        int kq = (t & 7) * 4;
        __half h0 = __float2half_rn(tl[kq + 0][t >> 3]);
        __half h1 = __float2half_rn(tl[kq + 1][t >> 3]);
        __half h2 = __float2half_rn(tl[kq + 2][t >> 3]);
        __half h3 = __float2half_rn(tl[kq + 3][t >> 3]);
        uint2 pk;
        pk.x = pack_h2(h0, h1);
        pk.y = pack_h2(h2, h3);
        *(uint2*)(T + (size_t)(rowoff + n) * K + k0 + kq) = pk;
    }
}

// ---------------- LayerNorm -> fp16 (LN2) ----------------
__global__ void layernorm_f16(const float* __restrict__ x, const float* __restrict__ g,
                              const float* __restrict__ b, __half* __restrict__ oh)
{
    __shared__ float red0[8], red1[8];
    int row = blockIdx.x, tid = threadIdx.x;
    const float4* xr = (const float4*)(x + (size_t)row * DD);
    float4 v = xr[tid];
    float s  = v.x + v.y + v.z + v.w;
    float s2 = v.x*v.x + v.y*v.y + v.z*v.z + v.w*v.w;
    #pragma unroll
    for (int o = 16; o; o >>= 1) {
        s  += __shfl_xor_sync(0xffffffffu, s,  o);
        s2 += __shfl_xor_sync(0xffffffffu, s2, o);
    }
    if ((tid & 31) == 0) { red0[tid >> 5] = s; red1[tid >> 5] = s2; }
    __syncthreads();
    float S = 0.f, S2 = 0.f;
    #pragma unroll
    for (int i = 0; i < 8; i++) { S += red0[i]; S2 += red1[i]; }
    float mean = S * (1.f / DD);
    float var  = S2 * (1.f / DD) - mean * mean;
    float rstd = rsqrtf(var + 1e-5f);
    float4 gv = ((const float4*)g)[tid];
    float4 bv = ((const float4*)b)[tid];
    float o0 = (v.x - mean) * rstd * gv.x + bv.x;
    float o1 = (v.y - mean) * rstd * gv.y + bv.y;
    float o2 = (v.z - mean) * rstd * gv.z + bv.z;
    float o3 = (v.w - mean) * rstd * gv.w + bv.w;
    size_t base = (size_t)row * DD + tid * 4;
    *(__half2*)(oh + base)     = __halves2half2(__float2half_rn(o0), __float2half_rn(o1));
    *(__half2*)(oh + base + 2) = __halves2half2(__float2half_rn(o2), __float2half_rn(o3));
}

// ---------------- tensor-core GEMM, fp16 1-pass, BK=64, 3-stage -----------
// block 128x128, 8 warps, warp tile 32x64, BK=64, 2 CTAs/SM.
// One __syncthreads per 64 K-elements (half R11's barrier density).
// Stage rows are 144B (conflict-free ldsm stride, as in flash).
// Group accounting: prologue loads stages 0,1 (groups 0,1). At top of iter
// kc outstanding = {kc, kc+1}; wait_group<=1 retires stage kc. After compute,
// load stage kc+2 into buf (kc+2)%3, last read in iter kc-1 (fenced by the
// top sync of iter kc).
#define LDB 144
#define A_SZ 18432            // 128 rows * 144
#define STG_SZ 36864
#define GSTAGES 3
template<int EPI>
__global__ void __launch_bounds__(256, 2)
gemm_mma(const __half* __restrict__ A, const __half* __restrict__ W,
         const float* __restrict__ bias, const float* __restrict__ res,
         float* __restrict__ C, __half* __restrict__ Ch,
         int M, int N, int K)
{
    extern __shared__ char smem[];
    const uint32_t sb = smem_u32(smem);
    const int tid = threadIdx.x;
    const int wid = tid >> 5, lane = tid & 31;
    const int wm = wid & 3, wn = wid >> 2;
    const int m0 = blockIdx.y * 128, n0 = blockIdx.x * 128;

    float acc[2][8][4] = {};
    const int NK = K >> 6;

    auto load_stage = [&](int kc, int buf) {
        int k0 = kc << 6;
        uint32_t stb = sb + buf * STG_SZ;
        #pragma unroll
        for (int i = 0; i < 8; i++) {
            int c = tid + i * 256;          // 0..2047
            int arr = c >> 10;              // 0:A 1:B
            int cc = c & 1023;
            int row = cc >> 3, col = cc & 7;
            const __half* gsrc = (arr ? W + (size_t)(n0 + row) * K
                                      : A + (size_t)(m0 + row) * K) + k0 + col * 8;
            cp_async16(stb + arr * A_SZ + row * LDB + col * 16, gsrc);
        }
    };

    // prologue: stages 0,1 (groups 0,1)
    load_stage(0, 0);
    asm volatile("cp.async.commit_group;" ::: "memory");
    load_stage(1, 1);
    asm volatile("cp.async.commit_group;" ::: "memory");

    for (int kc = 0; kc < NK; kc++) {
        asm volatile("cp.async.wait_group 1;" ::: "memory");
        __syncthreads();

        uint32_t stb = sb + (kc % 3) * STG_SZ;
        #pragma unroll
        for (int ks = 0; ks < 4; ks++) {
            uint32_t Af[2][4], Bf[8][2];
            int ar = lane & 15, ac = ks * 16 + (lane >> 4) * 8;
            #pragma unroll
            for (int mt = 0; mt < 2; mt++)
                ldsm_x4(Af[mt], stb + (wm * 32 + mt * 16 + ar) * LDB + ac * 2);
            int gq = lane >> 3, l8 = lane & 7;
            int br = (gq >> 1) * 8 + l8, bc = ks * 16 + (gq & 1) * 8;
            #pragma unroll
            for (int p = 0; p < 4; p++) {
                uint32_t a = stb + A_SZ + (wn * 64 + p * 16 + br) * LDB + bc * 2;
                uint32_t t[4];
                ldsm_x4(t, a);
                Bf[2*p][0] = t[0]; Bf[2*p][1] = t[1];
                Bf[2*p+1][0] = t[2]; Bf[2*p+1][1] = t[3];
            }
            #pragma unroll
            for (int mt = 0; mt < 2; mt++)
                #pragma unroll
                for (int nt = 0; nt < 8; nt++)
                    mma16816(acc[mt][nt], Af[mt], Bf[nt]);
        }

        // issue next stage (group kc+2); empty commit keeps group numbering
        if (kc + 2 < NK) load_stage(kc + 2, (kc + 2) % 3);
        asm volatile("cp.async.commit_group;" ::: "memory");
    }

    // ---- epilogue ----
    int rb = m0 + wm * 32 + (lane >> 2);
    int cb = n0 + wn * 64 + (lane & 3) * 2;
    #pragma unroll
    for (int mt = 0; mt < 2; mt++) {
        #pragma unroll
        for (int half = 0; half < 2; half++) {
            int r = rb + mt * 16 + half * 8;
            #pragma unroll
            for (int nt = 0; nt < 8; nt++) {
                int n = cb + nt * 8;
                float2 bv = *(const float2*)(bias + n);
                float v0 = acc[mt][nt][half * 2 + 0] + bv.x;
                float v1 = acc[mt][nt][half * 2 + 1] + bv.y;
                if (EPI == 2) {
                    float2 rv = *(const float2*)(res + (size_t)r * N + n);
                    v0 += rv.x; v1 += rv.y;
                    *(float2*)(C + (size_t)r * N + n) = make_float2(v0, v1);
                } else if (EPI == 3) {
                    v0 = 0.5f * v0 * (1.0f + erff(v0 * 0.70710678118654752f));
                    v1 = 0.5f * v1 * (1.0f + erff(v1 * 0.70710678118654752f));
                    *(__half2*)(Ch + (size_t)r * N + n) =
                        __halves2half2(__float2half_rn(v0), __float2half_rn(v1));
                } else if (EPI == 4) {
                    int which = n >> 10, n2 = n & 1023;
                    float scl = (which == 0) ? (1.0f / 32.0f) : 1.0f;
                    v0 *= scl; v1 *= scl;
                    int b_ = r >> 10, s = r & 1023, hh = n2 >> 6, dh = n2 & 63;
                    size_t off = (size_t)which * (ROWS * DD)
                               + ((size_t)(b_ * HH + hh) * SS + s) * DHH + dh;
                    *(__half2*)(Ch + off) =
                        __halves2half2(__float2half_rn(v0), __float2half_rn(v1));
                }
            }
        }
    }
}

// ---------------- Flash attention, fp16, 4-stage single-sync KV -----------
#define LDK 144
#define FQ_SZ 18432
#define FST0  18432
#define FARR  9216
#define FST_SZ 18432
#define FSTAGES 4
#define FLASH_SMEM (FST0 + FSTAGES*FST_SZ)   // 92160
__global__ void __launch_bounds__(256, 2)
flash_mma(const __half* __restrict__ Q_, const __half* __restrict__ K_,
          const __half* __restrict__ V_, __half* __restrict__ O_)
{
    extern __shared__ char smc[];
    const uint32_t sb = smem_u32(smc);
    int tid = threadIdx.x, lane = tid & 31, w = tid >> 5;
    int bh = blockIdx.y, q0 = blockIdx.x * 128;
    size_t qbase = ((size_t)bh * SS + q0) * DHH;
    size_t kvbase = (size_t)bh * SS * DHH;
    const int NT = SS / 64;

    // group 0: Q
    #pragma unroll
    for (int i = 0; i < 4; i++) {
        int c = tid + i * 256;
        int row = c >> 3, col = c & 7;
        cp_async16(sb + row * LDK + col * 16, Q_ + qbase + row * 64 + col * 8);
    }
    asm volatile("cp.async.commit_group;" ::: "memory");
    auto load_stage = [&](int t, int buf) {
        size_t base = kvbase + (size_t)t * 64 * DHH;
        #pragma unroll
        for (int i = 0; i < 4; i++) {
            int c = tid + i * 256;
            int arr = c >> 9, cc = c & 511;
            int row = cc >> 3, col = cc & 7;
            const __half* src = (arr ? V_ : K_) + base + row * 64 + col * 8;
            cp_async16(sb + FST0 + buf * FST_SZ + arr * FARR + row * LDK + col * 16, src);
        }
    };
    // groups 1..3: stages 0..2
    load_stage(0, 0);
    asm volatile("cp.async.commit_group;" ::: "memory");
    load_stage(1, 1);
    asm volatile("cp.async.commit_group;" ::: "memory");
    load_stage(2, 2);
    asm volatile("cp.async.commit_group;" ::: "memory");

    uint32_t qf[4][4];
    float m2[2] = {-1e30f, -1e30f}, l2[2] = {0.f, 0.f};
    float acc_o[8][4] = {};

    for (int t = 0; t < NT; t++) {
        asm volatile("cp.async.wait_group 2;" ::: "memory");
        __syncthreads();
        if (t == 0) {
            #pragma unroll
            for (int ks = 0; ks < 4; ks++)
                ldsm_x4(qf[ks], sb + (w * 16 + (lane & 15)) * LDK + ks * 32 + (lane >> 4) * 16);
        }
        uint32_t stb = sb + FST0 + (t & 3) * FST_SZ;

        float s[8][4] = {};
        int gq = lane >> 3, l8 = lane & 7;
        int br = (gq >> 1) * 8 + l8;
        #pragma unroll
        for (int ks = 0; ks < 4; ks++) {
            uint32_t Bf[8][2];
            int bcB = ks * 32 + (gq & 1) * 16;
            #pragma unroll
            for (int p = 0; p < 4; p++) {
                uint32_t a = stb + (p * 16 + br) * LDK + bcB;
                uint32_t t4[4];
                ldsm_x4(t4, a);
                Bf[2*p][0] = t4[0]; Bf[2*p][1] = t4[1];
                Bf[2*p+1][0] = t4[2]; Bf[2*p+1][1] = t4[3];
            }
            #pragma unroll
            for (int nt = 0; nt < 8; nt++)
                mma16816(s[nt], qf[ks], Bf[nt]);
        }

        float rm0 = -1e30f, rm1 = -1e30f;
        #pragma unroll
        for (int nt = 0; nt < 8; nt++) {
            rm0 = fmaxf(rm0, fmaxf(s[nt][0], s[nt][1]));
            rm1 = fmaxf(rm1, fmaxf(s[nt][2], s[nt][3]));
        }
        rm0 = fmaxf(rm0, __shfl_xor_sync(0xffffffffu, rm0, 1));
        rm0 = fmaxf(rm0, __shfl_xor_sync(0xffffffffu, rm0, 2));
        rm1 = fmaxf(rm1, __shfl_xor_sync(0xffffffffu, rm1, 1));
        rm1 = fmaxf(rm1, __shfl_xor_sync(0xffffffffu, rm1, 2));
        float mn0 = fmaxf(m2[0], rm0), mn1 = fmaxf(m2[1], rm1);
        float al0 = __expf(m2[0] - mn0), al1 = __expf(m2[1] - mn1);
        float rs0 = 0.f, rs1 = 0.f;
        #pragma unroll
        for (int nt = 0; nt < 8; nt++) {
            s[nt][0] = __expf(s[nt][0] - mn0);
            s[nt][1] = __expf(s[nt][1] - mn0);
            s[nt][2] = __expf(s[nt][2] - mn1);
            s[nt][3] = __expf(s[nt][3] - mn1);
            rs0 += s[nt][0] + s[nt][1];
            rs1 += s[nt][2] + s[nt][3];
        }
        rs0 += __shfl_xor_sync(0xffffffffu, rs0, 1);
        rs0 += __shfl_xor_sync(0xffffffffu, rs0, 2);
        rs1 += __shfl_xor_sync(0xffffffffu, rs1, 1);
        rs1 += __shfl_xor_sync(0xffffffffu, rs1, 2);
        l2[0] = l2[0] * al0 + rs0;
        l2[1] = l2[1] * al1 + rs1;
        m2[0] = mn0; m2[1] = mn1;
        #pragma unroll
        for (int nt = 0; nt < 8; nt++) {
            acc_o[nt][0] *= al0; acc_o[nt][1] *= al0;
            acc_o[nt][2] *= al1; acc_o[nt][3] *= al1;
        }

        int vr = ((lane >> 3) & 1) * 8 + (lane & 7);
        int vcb = ((lane >> 4) * 8) * 2;
        #pragma unroll
        for (int ks = 0; ks < 4; ks++) {
            uint32_t pf[4];
            #pragma unroll
            for (int q2 = 0; q2 < 2; q2++) {
                pf[2*q2]     = pack_h2(__float2half_rn(s[2*ks + q2][0]), __float2half_rn(s[2*ks + q2][1]));
                pf[2*q2 + 1] = pack_h2(__float2half_rn(s[2*ks + q2][2]), __float2half_rn(s[2*ks + q2][3]));
            }
            uint32_t Vf[8][2];
            #pragma unroll
            for (int np = 0; np < 4; np++) {
                uint32_t a = stb + FARR + (ks * 16 + vr) * LDK + np * 32 + vcb;
                uint32_t t4[4];
                ldsm_x4_t(t4, a);
                Vf[2*np][0] = t4[0]; Vf[2*np][1] = t4[1];
                Vf[2*np+1][0] = t4[2]; Vf[2*np+1][1] = t4[3];
            }
            #pragma unroll
            for (int nt = 0; nt < 8; nt++)
                mma16816(acc_o[nt], pf, Vf[nt]);
        }

        // issue next stage (group 4+t = stage t+3); empty commit otherwise
        if (t + 3 < NT) load_stage(t + 3, (t + 3) & 3);
        asm volatile("cp.async.commit_group;" ::: "memory");
    }

    float inv0 = 1.0f / l2[0], inv1 = 1.0f / l2[1];
    int g = lane >> 2;
    int bb = bh >> 4, hh = bh & 15;
    int r_lo = q0 + w * 16 + g, r_hi = r_lo + 8;
    int cbase = hh * 64 + (lane & 3) * 2;
    #pragma unroll
    for (int nt = 0; nt < 8; nt++) {
        int cc = cbase + nt * 8;
        size_t off_lo = ((size_t)bb * SS + r_lo) * DD + cc;
        size_t off_hi = ((size_t)bb * SS + r_hi) * DD + cc;
        *(__half2*)(O_ + off_lo) = __halves2half2(
            __float2half_rn(acc_o[nt][0] * inv0), __float2half_rn(acc_o[nt][1] * inv0));
        *(__half2*)(O_ + off_hi) = __halves2half2(
            __float2half_rn(acc_o[nt][2] * inv1), __float2half_rn(acc_o[nt][3] * inv1));
    }
}

// ---------------- launch ----------------
extern "C" void kernel_launch(void* const* d_in, const int* in_sizes, int n_in,
                              void* d_out, int out_size)
{
    const float* x    = (const float*)d_in[0];
    const float* wq   = (const float*)d_in[1];
    const float* bq   = (const float*)d_in[2];
    const float* wk   = (const float*)d_in[3];
    const float* bk   = (const float*)d_in[4];
    const float* wv   = (const float*)d_in[5];
    const float* bv   = (const float*)d_in[6];
    const float* wo   = (const float*)d_in[7];
    const float* bo   = (const float*)d_in[8];
    const float* g1   = (const float*)d_in[9];
    const float* b1   = (const float*)d_in[10];
    const float* g2   = (const float*)d_in[11];
    const float* b2   = (const float*)d_in[12];
    const float* wfc1 = (const float*)d_in[13];
    const float* bfc1 = (const float*)d_in[14];
    const float* wfc2 = (const float*)d_in[15];
    const float* bfc2 = (const float*)d_in[16];
    float* out = (float*)d_out;

    float *o1, *bqkv;
    cudaGetSymbolAddress((void**)&o1,   g_o1);
    cudaGetSymbolAddress((void**)&bqkv, g_bqkv);
    __half *xa, *mid, *qkv;
    cudaGetSymbolAddress((void**)&xa,  g_x);
    cudaGetSymbolAddress((void**)&mid, g_mid);
    cudaGetSymbolAddress((void**)&qkv, g_qkv);
    __half *wqkvt, *wot, *w1t, *w2t;
    cudaGetSymbolAddress((void**)&wqkvt, g_wqkvt);
    cudaGetSymbolAddress((void**)&wot,   g_wot);
    cudaGetSymbolAddress((void**)&w1t,   g_w1t);
    cudaGetSymbolAddress((void**)&w2t,   g_w2t);

    const int GEMM_SMEM = GSTAGES * STG_SZ;  // 110592
    cudaFuncSetAttribute(gemm_mma<2>, cudaFuncAttributeMaxDynamicSharedMemorySize, GEMM_SMEM);
    cudaFuncSetAttribute(gemm_mma<3>, cudaFuncAttributeMaxDynamicSharedMemorySize, GEMM_SMEM);
    cudaFuncSetAttribute(gemm_mma<4>, cudaFuncAttributeMaxDynamicSharedMemorySize, GEMM_SMEM);
    cudaFuncSetAttribute(flash_mma, cudaFuncAttributeMaxDynamicSharedMemorySize, FLASH_SMEM);

    // 0. weights + bias pack + LN1, one launch
    wconv_all<<<16385, dim3(32, 8)>>>(wq, wk, wv, wo, wfc1, wfc2, bq, bk, bv,
                                      x, g1, b1, xa);

    // 1. fused QKV projection -> (3,B,H,S,DH) fp16
    gemm_mma<4><<<dim3(3 * DD / 128, ROWS / 128), 256, GEMM_SMEM>>>(
        xa, wqkvt, bqkv, nullptr, nullptr, qkv, ROWS, 3 * DD, DD);

    // 2. attention -> fp16 (B,S,D) into xa
    flash_mma<<<dim3(SS / 128, BB * HH), 256, FLASH_SMEM>>>(
        qkv, qkv + ROWS * DD, qkv + 2 * ROWS * DD, xa);

    // 3. output projection + residual(x) -> o1 fp32
    gemm_mma<2><<<dim3(DD / 128, ROWS / 128), 256, GEMM_SMEM>>>(
        xa, wot, bo, x, o1, nullptr, ROWS, DD, DD);

    // 4. LN2 -> fp16
    layernorm_f16<<<ROWS, 256>>>(o1, g2, b2, xa);

    // 5. FC1 + GELU -> fp16 mid
    gemm_mma<3><<<dim3(FFN / 128, ROWS / 128), 256, GEMM_SMEM>>>(
        xa, w1t, bfc1, nullptr, nullptr, mid, ROWS, FFN, DD);

    // 6. FC2 + residual(o1) -> out
    gemm_mma<2><<<dim3(DD / 128, ROWS / 128), 256, GEMM_SMEM>>>(
        mid, w2t, bfc2, o1, out, nullptr, ROWS, DD, FFN);
}